// round 2
// baseline (speedup 1.0000x reference)
#include <cuda_runtime.h>

#define NTOK 144
#define HEADS 4
#define DH 32
#define CC 384
#define MB 48          // query rows per CTA (144 = 3 * 48)
#define QSS 36         // Q smem stride (floats)
#define KSS 36
#define VSS 36
#define SSS 148        // S smem stride
#define SCALE 0.17677669529663687f

// SMEM: Q 48x36 + K 144x36 + V 144x36 + S 48x148 = 19200 floats = 76800 B
#define SMEM_FLOATS (MB*QSS + NTOK*KSS + NTOK*VSS + MB*SSS)

__global__ __launch_bounds__(256, 2)
void attn_kernel(const float* __restrict__ qkv,
                 const float* __restrict__ mask,
                 float* __restrict__ out) {
    extern __shared__ float sm[];
    float* Qs = sm;                    // MB x QSS
    float* Ks = Qs + MB * QSS;         // NTOK x KSS
    float* Vs = Ks + NTOK * KSS;       // NTOK x VSS
    float* Ss = Vs + NTOK * VSS;       // MB x SSS

    const int mblk = blockIdx.x;
    const int h    = blockIdx.y;
    const int b    = blockIdx.z;
    const int tid  = threadIdx.x;
    const int m0   = mblk * MB;

    const float* base = qkv + (size_t)b * NTOK * CC;

    // ---- Load K, V tiles (144 x 32 each), 8 float4 per row ----
    for (int i = tid; i < NTOK * 8; i += 256) {
        int r = i >> 3, f = (i & 7) * 4;
        *(float4*)(Ks + r * KSS + f) =
            *(const float4*)(base + r * CC + 128 + h * DH + f);
        *(float4*)(Vs + r * VSS + f) =
            *(const float4*)(base + r * CC + 256 + h * DH + f);
    }
    // ---- Load Q tile (48 x 32) ----
    for (int i = tid; i < MB * 8; i += 256) {
        int r = i >> 3, f = (i & 7) * 4;
        *(float4*)(Qs + r * QSS + f) =
            *(const float4*)(base + (size_t)(m0 + r) * CC + h * DH + f);
    }
    __syncthreads();

    // ---- S = Q K^T  (48 x 144, k=32), 3x9 per-thread register tile ----
    {
        const int ty = tid >> 4;    // 0..15
        const int tx = tid & 15;    // 0..15
        float acc[3][9];
        #pragma unroll
        for (int i = 0; i < 3; i++)
            #pragma unroll
            for (int j = 0; j < 9; j++)
                acc[i][j] = 0.0f;

        #pragma unroll
        for (int k = 0; k < DH; k += 4) {
            float4 qv[3];
            #pragma unroll
            for (int i = 0; i < 3; i++)
                qv[i] = *(float4*)(Qs + (ty + 16 * i) * QSS + k);
            #pragma unroll
            for (int j = 0; j < 9; j++) {
                float4 kv = *(float4*)(Ks + (tx + 16 * j) * KSS + k);
                #pragma unroll
                for (int i = 0; i < 3; i++) {
                    acc[i][j] += qv[i].x * kv.x + qv[i].y * kv.y
                               + qv[i].z * kv.z + qv[i].w * kv.w;
                }
            }
        }
        const float* mrow = mask + ((size_t)h * NTOK + m0) * NTOK;
        #pragma unroll
        for (int i = 0; i < 3; i++) {
            int r = ty + 16 * i;
            #pragma unroll
            for (int j = 0; j < 9; j++) {
                int c = tx + 16 * j;
                Ss[r * SSS + c] = acc[i][j] * SCALE + mrow[r * NTOK + c];
            }
        }
    }
    __syncthreads();

    // ---- Row softmax: warp per 6 rows ----
    const int w = tid >> 5, lane = tid & 31;
    #pragma unroll
    for (int rr = 0; rr < 6; rr++) {
        int r = w * 6 + rr;
        float v[5];
        #pragma unroll
        for (int c = 0; c < 5; c++) {
            int col = lane + 32 * c;
            v[c] = (col < NTOK) ? Ss[r * SSS + col] : -1e30f;
        }
        float mx = v[0];
        #pragma unroll
        for (int c = 1; c < 5; c++) mx = fmaxf(mx, v[c]);
        #pragma unroll
        for (int off = 16; off > 0; off >>= 1)
            mx = fmaxf(mx, __shfl_xor_sync(0xFFFFFFFFu, mx, off));
        float s = 0.0f;
        #pragma unroll
        for (int c = 0; c < 5; c++) { v[c] = __expf(v[c] - mx); s += v[c]; }
        #pragma unroll
        for (int off = 16; off > 0; off >>= 1)
            s += __shfl_xor_sync(0xFFFFFFFFu, s, off);
        float inv = 1.0f / s;
        #pragma unroll
        for (int c = 0; c < 5; c++) {
            int col = lane + 32 * c;
            if (col < NTOK) Ss[r * SSS + col] = v[c] * inv;
        }
    }
    __syncthreads();

    // ---- O = P V  (48 x 32): lane owns one output column ----
    {
        float acc[6] = {0, 0, 0, 0, 0, 0};
        #pragma unroll 4
        for (int k = 0; k < NTOK; k += 4) {
            float vv[4];
            #pragma unroll
            for (int kk = 0; kk < 4; kk++)
                vv[kk] = Vs[(k + kk) * VSS + lane];
            #pragma unroll
            for (int rr = 0; rr < 6; rr++) {
                float4 p = *(float4*)(Ss + (w * 6 + rr) * SSS + k);
                acc[rr] += p.x * vv[0] + p.y * vv[1] + p.z * vv[2] + p.w * vv[3];
            }
        }
        #pragma unroll
        for (int rr = 0; rr < 6; rr++) {
            out[((size_t)b * NTOK + m0 + w * 6 + rr) * 128 + h * DH + lane] = acc[rr];
        }
    }
}

extern "C" void kernel_launch(void* const* d_in, const int* in_sizes, int n_in,
                              void* d_out, int out_size) {
    const float* qkv  = (const float*)d_in[0];
    const float* mask = (const float*)d_in[1];
    float* out = (float*)d_out;

    cudaFuncSetAttribute(attn_kernel,
                         cudaFuncAttributeMaxDynamicSharedMemorySize,
                         SMEM_FLOATS * (int)sizeof(float));

    dim3 grid(NTOK / MB, HEADS, 2048);
    attn_kernel<<<grid, 256, SMEM_FLOATS * sizeof(float)>>>(qkv, mask, out);
}

// round 3
// speedup vs baseline: 1.3732x; 1.3732x over previous
#include <cuda_runtime.h>
#include <cuda_bf16.h>
#include <cstdint>

#define NTOK 144
#define HEADS 4
#define DH 32
#define CC 384
#define MB 48
#define SCALE 0.17677669529663687f

#define QKV_STR 40     // bf16 elems per row (80B) -> ldmatrix conflict-free
#define S_STR   148    // fp32 elems
#define P_STR   152    // bf16 elems (304B) -> ldmatrix conflict-free

// smem byte offsets
#define OFF_QHI 0
#define OFF_QLO (OFF_QHI + MB*QKV_STR*2)        // 3840
#define OFF_KHI (OFF_QLO + MB*QKV_STR*2)        // 7680
#define OFF_KLO (OFF_KHI + NTOK*QKV_STR*2)      // 19200
#define OFF_VHI (OFF_KLO + NTOK*QKV_STR*2)      // 30720
#define OFF_VLO (OFF_VHI + NTOK*QKV_STR*2)      // 42240
#define OFF_S   (OFF_VLO + NTOK*QKV_STR*2)      // 53760  (fp32 S, 48x148 = 28416B)
#define OFF_PHI OFF_S                           // P overlays S (after reg-buffered softmax)
#define OFF_PLO (OFF_PHI + MB*P_STR*2)          // +14592
#define SMEM_BYTES (OFF_S + 2*MB*P_STR*2)       // 82944

#define LDSM4(r0,r1,r2,r3,addr) \
    asm volatile("ldmatrix.sync.aligned.m8n8.x4.shared.b16 {%0,%1,%2,%3}, [%4];" \
        : "=r"(r0),"=r"(r1),"=r"(r2),"=r"(r3) : "r"(addr))
#define LDSM4T(r0,r1,r2,r3,addr) \
    asm volatile("ldmatrix.sync.aligned.m8n8.x4.trans.shared.b16 {%0,%1,%2,%3}, [%4];" \
        : "=r"(r0),"=r"(r1),"=r"(r2),"=r"(r3) : "r"(addr))
#define LDSM2T(r0,r1,addr) \
    asm volatile("ldmatrix.sync.aligned.m8n8.x2.trans.shared.b16 {%0,%1}, [%2];" \
        : "=r"(r0),"=r"(r1) : "r"(addr))
#define MMA16816(c0,c1,c2,c3,a0,a1,a2,a3,b0,b1) \
    asm volatile("mma.sync.aligned.m16n8k16.row.col.f32.bf16.bf16.f32 " \
        "{%0,%1,%2,%3}, {%4,%5,%6,%7}, {%8,%9}, {%0,%1,%2,%3};" \
        : "+f"(c0),"+f"(c1),"+f"(c2),"+f"(c3) \
        : "r"(a0),"r"(a1),"r"(a2),"r"(a3),"r"(b0),"r"(b1))

__device__ __forceinline__ void split_store(float4 v, __nv_bfloat16* hi, __nv_bfloat16* lo) {
    __nv_bfloat16 h0 = __float2bfloat16(v.x), h1 = __float2bfloat16(v.y);
    __nv_bfloat16 h2 = __float2bfloat16(v.z), h3 = __float2bfloat16(v.w);
    __nv_bfloat16 l0 = __float2bfloat16(v.x - __bfloat162float(h0));
    __nv_bfloat16 l1 = __float2bfloat16(v.y - __bfloat162float(h1));
    __nv_bfloat16 l2 = __float2bfloat16(v.z - __bfloat162float(h2));
    __nv_bfloat16 l3 = __float2bfloat16(v.w - __bfloat162float(h3));
    union U { __nv_bfloat16 b[4]; uint2 u; };
    U H, L;
    H.b[0]=h0; H.b[1]=h1; H.b[2]=h2; H.b[3]=h3;
    L.b[0]=l0; L.b[1]=l1; L.b[2]=l2; L.b[3]=l3;
    *(uint2*)hi = H.u;
    *(uint2*)lo = L.u;
}

__global__ __launch_bounds__(256, 2)
void attn_kernel(const float* __restrict__ qkv,
                 const float* __restrict__ mask,
                 float* __restrict__ out) {
    extern __shared__ char smc[];
    const uint32_t smb = (uint32_t)__cvta_generic_to_shared(smc);

    const int mblk = blockIdx.x, h = blockIdx.y, b = blockIdx.z;
    const int tid = threadIdx.x;
    const int w = tid >> 5, lane = tid & 31;
    const int m0 = mblk * MB;

    const float* base = qkv + (size_t)b * NTOK * CC;

    __nv_bfloat16* Qhi = (__nv_bfloat16*)(smc + OFF_QHI);
    __nv_bfloat16* Qlo = (__nv_bfloat16*)(smc + OFF_QLO);
    __nv_bfloat16* Khi = (__nv_bfloat16*)(smc + OFF_KHI);
    __nv_bfloat16* Klo = (__nv_bfloat16*)(smc + OFF_KLO);
    __nv_bfloat16* Vhi = (__nv_bfloat16*)(smc + OFF_VHI);
    __nv_bfloat16* Vlo = (__nv_bfloat16*)(smc + OFF_VLO);
    float* Sf = (float*)(smc + OFF_S);
    __nv_bfloat16* Phi = (__nv_bfloat16*)(smc + OFF_PHI);
    __nv_bfloat16* Plo = (__nv_bfloat16*)(smc + OFF_PLO);

    // ---- Phase 1: load K,V,Q; split to bf16 hi/lo ----
    for (int i = tid; i < NTOK * 8; i += 256) {
        int r = i >> 3, f = (i & 7) * 4;
        float4 kv = *(const float4*)(base + r * CC + 128 + h * DH + f);
        split_store(kv, Khi + r * QKV_STR + f, Klo + r * QKV_STR + f);
        float4 vv = *(const float4*)(base + r * CC + 256 + h * DH + f);
        split_store(vv, Vhi + r * QKV_STR + f, Vlo + r * QKV_STR + f);
    }
    for (int i = tid; i < MB * 8; i += 256) {
        int r = i >> 3, f = (i & 7) * 4;
        float4 qv = *(const float4*)(base + (size_t)(m0 + r) * CC + h * DH + f);
        split_store(qv, Qhi + r * QKV_STR + f, Qlo + r * QKV_STR + f);
    }
    __syncthreads();

    // ---- Phase 2: S = scale * Q K^T + mask  (tensor, 3-MMA bf16 split) ----
    if (w < 6) {
        const int wm = w >> 1;          // m-tile 0..2 (16 rows each)
        const int wn = w & 1;           // n half (9 n-tiles each)
        const uint32_t arow = (uint32_t)((wm * 16 + (lane & 15)) * QKV_STR + (lane >> 4) * 8);
        uint32_t ah[2][4], al[2][4];
        #pragma unroll
        for (int ki = 0; ki < 2; ki++) {
            LDSM4(ah[ki][0], ah[ki][1], ah[ki][2], ah[ki][3],
                  smb + OFF_QHI + (arow + ki * 16) * 2);
            LDSM4(al[ki][0], al[ki][1], al[ki][2], al[ki][3],
                  smb + OFF_QLO + (arow + ki * 16) * 2);
        }
        const float* mh = mask + (size_t)h * NTOK * NTOK;
        const int qr0 = wm * 16 + (lane >> 2);
        #pragma unroll
        for (int j = 0; j < 9; j++) {
            const int n0 = (wn * 9 + j) * 8;
            const uint32_t brow = (uint32_t)((n0 + (lane & 7)) * QKV_STR + (lane >> 3) * 8);
            uint32_t bh[4], bl[4];
            LDSM4(bh[0], bh[1], bh[2], bh[3], smb + OFF_KHI + brow * 2);
            LDSM4(bl[0], bl[1], bl[2], bl[3], smb + OFF_KLO + brow * 2);
            float c0 = 0.f, c1 = 0.f, c2 = 0.f, c3 = 0.f;
            MMA16816(c0,c1,c2,c3, ah[0][0],ah[0][1],ah[0][2],ah[0][3], bh[0],bh[1]);
            MMA16816(c0,c1,c2,c3, ah[1][0],ah[1][1],ah[1][2],ah[1][3], bh[2],bh[3]);
            MMA16816(c0,c1,c2,c3, ah[0][0],ah[0][1],ah[0][2],ah[0][3], bl[0],bl[1]);
            MMA16816(c0,c1,c2,c3, ah[1][0],ah[1][1],ah[1][2],ah[1][3], bl[2],bl[3]);
            MMA16816(c0,c1,c2,c3, al[0][0],al[0][1],al[0][2],al[0][3], bh[0],bh[1]);
            MMA16816(c0,c1,c2,c3, al[1][0],al[1][1],al[1][2],al[1][3], bh[2],bh[3]);
            const int col = n0 + (lane & 3) * 2;
            float2 mv0 = *(const float2*)(mh + (size_t)(m0 + qr0) * NTOK + col);
            float2 mv1 = *(const float2*)(mh + (size_t)(m0 + qr0 + 8) * NTOK + col);
            *(float2*)(Sf + qr0 * S_STR + col) =
                make_float2(c0 * SCALE + mv0.x, c1 * SCALE + mv0.y);
            *(float2*)(Sf + (qr0 + 8) * S_STR + col) =
                make_float2(c2 * SCALE + mv1.x, c3 * SCALE + mv1.y);
        }
    }
    __syncthreads();

    // ---- Phase 3: softmax (warp per 6 rows), P -> bf16 hi/lo (overlays S) ----
    {
        float vbuf[6][5];
        #pragma unroll
        for (int rr = 0; rr < 6; rr++) {
            const int r = w * 6 + rr;
            float v[5];
            #pragma unroll
            for (int c = 0; c < 5; c++) {
                int col = lane + 32 * c;
                v[c] = (col < NTOK) ? Sf[r * S_STR + col] : -1e30f;
            }
            float mx = v[0];
            #pragma unroll
            for (int c = 1; c < 5; c++) mx = fmaxf(mx, v[c]);
            #pragma unroll
            for (int off = 16; off > 0; off >>= 1)
                mx = fmaxf(mx, __shfl_xor_sync(0xFFFFFFFFu, mx, off));
            float s = 0.f;
            #pragma unroll
            for (int c = 0; c < 5; c++) { v[c] = __expf(v[c] - mx); s += v[c]; }
            #pragma unroll
            for (int off = 16; off > 0; off >>= 1)
                s += __shfl_xor_sync(0xFFFFFFFFu, s, off);
            float inv = 1.0f / s;
            #pragma unroll
            for (int c = 0; c < 5; c++) vbuf[rr][c] = v[c] * inv;
        }
        __syncthreads();   // all S reads complete before P overlays it
        #pragma unroll
        for (int rr = 0; rr < 6; rr++) {
            const int r = w * 6 + rr;
            #pragma unroll
            for (int c = 0; c < 5; c++) {
                int col = lane + 32 * c;
                if (col < NTOK) {
                    float p = vbuf[rr][c];
                    __nv_bfloat16 ph = __float2bfloat16(p);
                    Phi[r * P_STR + col] = ph;
                    Plo[r * P_STR + col] = __float2bfloat16(p - __bfloat162float(ph));
                }
            }
        }
    }
    __syncthreads();

    // ---- Phase 4: O = P V  (tensor, 3-MMA bf16 split) ----
    if (w < 6) {
        const int mt = w >> 1;              // m-tile 0..2
        const int nb = (w & 1) * 16;        // two n-tiles: nb, nb+8
        float cA[4] = {0,0,0,0}, cB[4] = {0,0,0,0};
        const uint32_t parow = (uint32_t)((mt * 16 + (lane & 15)) * P_STR + (lane >> 4) * 8);

        #pragma unroll
        for (int kp = 0; kp < 4; kp++) {
            const int k0 = kp * 32;
            uint32_t aha[4], ahb[4], ala[4], alb[4];
            LDSM4(aha[0],aha[1],aha[2],aha[3], smb + OFF_PHI + (parow + k0) * 2);
            LDSM4(ahb[0],ahb[1],ahb[2],ahb[3], smb + OFF_PHI + (parow + k0 + 16) * 2);
            LDSM4(ala[0],ala[1],ala[2],ala[3], smb + OFF_PLO + (parow + k0) * 2);
            LDSM4(alb[0],alb[1],alb[2],alb[3], smb + OFF_PLO + (parow + k0 + 16) * 2);
            const uint32_t vrow = (uint32_t)((k0 + lane) * QKV_STR);
            uint32_t bh0[4], bl0[4], bh1[4], bl1[4];
            LDSM4T(bh0[0],bh0[1],bh0[2],bh0[3], smb + OFF_VHI + (vrow + nb) * 2);
            LDSM4T(bl0[0],bl0[1],bl0[2],bl0[3], smb + OFF_VLO + (vrow + nb) * 2);
            LDSM4T(bh1[0],bh1[1],bh1[2],bh1[3], smb + OFF_VHI + (vrow + nb + 8) * 2);
            LDSM4T(bl1[0],bl1[1],bl1[2],bl1[3], smb + OFF_VLO + (vrow + nb + 8) * 2);
            MMA16816(cA[0],cA[1],cA[2],cA[3], aha[0],aha[1],aha[2],aha[3], bh0[0],bh0[1]);
            MMA16816(cA[0],cA[1],cA[2],cA[3], ahb[0],ahb[1],ahb[2],ahb[3], bh0[2],bh0[3]);
            MMA16816(cA[0],cA[1],cA[2],cA[3], aha[0],aha[1],aha[2],aha[3], bl0[0],bl0[1]);
            MMA16816(cA[0],cA[1],cA[2],cA[3], ahb[0],ahb[1],ahb[2],ahb[3], bl0[2],bl0[3]);
            MMA16816(cA[0],cA[1],cA[2],cA[3], ala[0],ala[1],ala[2],ala[3], bh0[0],bh0[1]);
            MMA16816(cA[0],cA[1],cA[2],cA[3], alb[0],alb[1],alb[2],alb[3], bh0[2],bh0[3]);
            MMA16816(cB[0],cB[1],cB[2],cB[3], aha[0],aha[1],aha[2],aha[3], bh1[0],bh1[1]);
            MMA16816(cB[0],cB[1],cB[2],cB[3], ahb[0],ahb[1],ahb[2],ahb[3], bh1[2],bh1[3]);
            MMA16816(cB[0],cB[1],cB[2],cB[3], aha[0],aha[1],aha[2],aha[3], bl1[0],bl1[1]);
            MMA16816(cB[0],cB[1],cB[2],cB[3], ahb[0],ahb[1],ahb[2],ahb[3], bl1[2],bl1[3]);
            MMA16816(cB[0],cB[1],cB[2],cB[3], ala[0],ala[1],ala[2],ala[3], bh1[0],bh1[1]);
            MMA16816(cB[0],cB[1],cB[2],cB[3], alb[0],alb[1],alb[2],alb[3], bh1[2],bh1[3]);
        }
        {   // tail k-iter: k0 = 128 (16 k)
            const int k0 = 128;
            uint32_t ah[4], al[4];
            LDSM4(ah[0],ah[1],ah[2],ah[3], smb + OFF_PHI + (parow + k0) * 2);
            LDSM4(al[0],al[1],al[2],al[3], smb + OFF_PLO + (parow + k0) * 2);
            const uint32_t vrow = (uint32_t)((k0 + (lane & 15)) * QKV_STR);
            uint32_t bh0[2], bl0[2], bh1[2], bl1[2];
            LDSM2T(bh0[0],bh0[1], smb + OFF_VHI + (vrow + nb) * 2);
            LDSM2T(bl0[0],bl0[1], smb + OFF_VLO + (vrow + nb) * 2);
            LDSM2T(bh1[0],bh1[1], smb + OFF_VHI + (vrow + nb + 8) * 2);
            LDSM2T(bl1[0],bl1[1], smb + OFF_VLO + (vrow + nb + 8) * 2);
            MMA16816(cA[0],cA[1],cA[2],cA[3], ah[0],ah[1],ah[2],ah[3], bh0[0],bh0[1]);
            MMA16816(cA[0],cA[1],cA[2],cA[3], ah[0],ah[1],ah[2],ah[3], bl0[0],bl0[1]);
            MMA16816(cA[0],cA[1],cA[2],cA[3], al[0],al[1],al[2],al[3], bh0[0],bh0[1]);
            MMA16816(cB[0],cB[1],cB[2],cB[3], ah[0],ah[1],ah[2],ah[3], bh1[0],bh1[1]);
            MMA16816(cB[0],cB[1],cB[2],cB[3], ah[0],ah[1],ah[2],ah[3], bl1[0],bl1[1]);
            MMA16816(cB[0],cB[1],cB[2],cB[3], al[0],al[1],al[2],al[3], bh1[0],bh1[1]);
        }
        const int qr = m0 + mt * 16 + (lane >> 2);
        const int col = h * DH + nb + (lane & 3) * 2;
        *(float2*)(out + ((size_t)b * NTOK + qr) * 128 + col)     = make_float2(cA[0], cA[1]);
        *(float2*)(out + ((size_t)b * NTOK + qr + 8) * 128 + col) = make_float2(cA[2], cA[3]);
        *(float2*)(out + ((size_t)b * NTOK + qr) * 128 + col + 8) = make_float2(cB[0], cB[1]);
        *(float2*)(out + ((size_t)b * NTOK + qr + 8) * 128 + col + 8) = make_float2(cB[2], cB[3]);
    }
}

extern "C" void kernel_launch(void* const* d_in, const int* in_sizes, int n_in,
                              void* d_out, int out_size) {
    const float* qkv  = (const float*)d_in[0];
    const float* mask = (const float*)d_in[1];
    float* out = (float*)d_out;

    cudaFuncSetAttribute(attn_kernel,
                         cudaFuncAttributeMaxDynamicSharedMemorySize, SMEM_BYTES);

    dim3 grid(NTOK / MB, HEADS, 2048);
    attn_kernel<<<grid, 256, SMEM_BYTES>>>(qkv, mask, out);
}

// round 6
// speedup vs baseline: 3.2510x; 2.3674x over previous
#include <cuda_runtime.h>
#include <cuda_bf16.h>
#include <cstdint>

#define NTOK 144
#define HEADS 4
#define CC 384
#define DH 32
#define STR 40             // bf16 elems per smem row (80B) -> ldmatrix conflict-free
#define SCALE 0.17677669529663687f

#define TSZ (NTOK*STR*2)   // 11520 B per tensor plane
#define OFF_QHI 0
#define OFF_QLO (1*TSZ)
#define OFF_KHI (2*TSZ)
#define OFF_KLO (3*TSZ)
#define OFF_VHI (4*TSZ)
#define OFF_VLO (5*TSZ)
#define SMEM_BYTES (6*TSZ) // 69120 B

#define LDSM4(r0,r1,r2,r3,addr) \
    asm volatile("ldmatrix.sync.aligned.m8n8.x4.shared.b16 {%0,%1,%2,%3}, [%4];" \
        : "=r"(r0),"=r"(r1),"=r"(r2),"=r"(r3) : "r"(addr))
#define LDSM4T(r0,r1,r2,r3,addr) \
    asm volatile("ldmatrix.sync.aligned.m8n8.x4.trans.shared.b16 {%0,%1,%2,%3}, [%4];" \
        : "=r"(r0),"=r"(r1),"=r"(r2),"=r"(r3) : "r"(addr))
#define LDSM2T(r0,r1,addr) \
    asm volatile("ldmatrix.sync.aligned.m8n8.x2.trans.shared.b16 {%0,%1}, [%2];" \
        : "=r"(r0),"=r"(r1) : "r"(addr))
#define MMA16816(c,a0,a1,a2,a3,b0,b1) \
    asm volatile("mma.sync.aligned.m16n8k16.row.col.f32.bf16.bf16.f32 " \
        "{%0,%1,%2,%3}, {%4,%5,%6,%7}, {%8,%9}, {%0,%1,%2,%3};" \
        : "+f"(c[0]),"+f"(c[1]),"+f"(c[2]),"+f"(c[3]) \
        : "r"(a0),"r"(a1),"r"(a2),"r"(a3),"r"(b0),"r"(b1))
#define MMA16808(c,a0,a1,b0) \
    asm volatile("mma.sync.aligned.m16n8k8.row.col.f32.bf16.bf16.f32 " \
        "{%0,%1,%2,%3}, {%4,%5}, {%6}, {%0,%1,%2,%3};" \
        : "+f"(c[0]),"+f"(c[1]),"+f"(c[2]),"+f"(c[3]) \
        : "r"(a0),"r"(a1),"r"(b0))

// exp on fma/alu pipes (no MUFU): 2^(x*log2e), deg-5 poly + exponent-bit scale
__device__ __forceinline__ float fexp(float x) {
    x = fmaxf(x, -80.0f);
    float t = x * 1.4426950408889634f;
    float r = rintf(t);
    float f = t - r;
    float p = 1.33336498e-3f;
    p = fmaf(p, f, 9.61793571e-3f);
    p = fmaf(p, f, 5.55043442e-2f);
    p = fmaf(p, f, 2.40226507e-1f);
    p = fmaf(p, f, 6.93147182e-1f);
    p = fmaf(p, f, 1.0f);
    return __int_as_float(__float_as_int(p) + (((int)r) << 23));
}

__device__ __forceinline__ void split_store(float4 v, __nv_bfloat16* hi, __nv_bfloat16* lo) {
    __nv_bfloat16 h0 = __float2bfloat16(v.x), h1 = __float2bfloat16(v.y);
    __nv_bfloat16 h2 = __float2bfloat16(v.z), h3 = __float2bfloat16(v.w);
    __nv_bfloat16 l0 = __float2bfloat16(v.x - __bfloat162float(h0));
    __nv_bfloat16 l1 = __float2bfloat16(v.y - __bfloat162float(h1));
    __nv_bfloat16 l2 = __float2bfloat16(v.z - __bfloat162float(h2));
    __nv_bfloat16 l3 = __float2bfloat16(v.w - __bfloat162float(h3));
    union U { __nv_bfloat16 b[4]; uint2 u; };
    U H, L;
    H.b[0]=h0; H.b[1]=h1; H.b[2]=h2; H.b[3]=h3;
    L.b[0]=l0; L.b[1]=l1; L.b[2]=l2; L.b[3]=l3;
    *(uint2*)hi = H.u; *(uint2*)lo = L.u;
}

__device__ __forceinline__ void split2(float a, float b, uint32_t& hi, uint32_t& lo) {
    __nv_bfloat16 ha = __float2bfloat16(a), hb = __float2bfloat16(b);
    __nv_bfloat16 la = __float2bfloat16(a - __bfloat162float(ha));
    __nv_bfloat16 lb = __float2bfloat16(b - __bfloat162float(hb));
    union U { __nv_bfloat16 b[2]; uint32_t u; };
    U H, L;
    H.b[0] = ha; H.b[1] = hb;
    L.b[0] = la; L.b[1] = lb;
    hi = H.u; lo = L.u;
}

__global__ __launch_bounds__(288, 2)
void attn_kernel(const float* __restrict__ qkv,
                 const float* __restrict__ mask,
                 float* __restrict__ out)
{
    extern __shared__ char smc[];
    const uint32_t smb = (uint32_t)__cvta_generic_to_shared(smc);
    const int h = blockIdx.x, b = blockIdx.y;
    const int tid = threadIdx.x, w = tid >> 5, lane = tid & 31;
    const int g = lane >> 2, tig = lane & 3;

    __nv_bfloat16* Qhi = (__nv_bfloat16*)(smc + OFF_QHI);
    __nv_bfloat16* Qlo = (__nv_bfloat16*)(smc + OFF_QLO);
    __nv_bfloat16* Khi = (__nv_bfloat16*)(smc + OFF_KHI);
    __nv_bfloat16* Klo = (__nv_bfloat16*)(smc + OFF_KLO);
    __nv_bfloat16* Vhi = (__nv_bfloat16*)(smc + OFF_VHI);
    __nv_bfloat16* Vlo = (__nv_bfloat16*)(smc + OFF_VLO);

    // ---- load Q (pre-scaled), K, V; split fp32 -> bf16 hi/lo ----
    const float* base = qkv + (size_t)b * NTOK * CC;
    for (int i = tid; i < NTOK * 8; i += 288) {
        int r = i >> 3, f = (i & 7) * 4;
        float4 qv = *(const float4*)(base + r * CC + h * DH + f);
        qv.x *= SCALE; qv.y *= SCALE; qv.z *= SCALE; qv.w *= SCALE;
        split_store(qv, Qhi + r * STR + f, Qlo + r * STR + f);
        float4 kv = *(const float4*)(base + r * CC + 128 + h * DH + f);
        split_store(kv, Khi + r * STR + f, Klo + r * STR + f);
        float4 vv = *(const float4*)(base + r * CC + 256 + h * DH + f);
        split_store(vv, Vhi + r * STR + f, Vlo + r * STR + f);
    }
    __syncthreads();

    // ---- Q A-fragments (k=32 -> two k16 frags), hi and lo ----
    const uint32_t arow2 = (uint32_t)(((16 * w + (lane & 15)) * STR + (lane >> 4) * 8) * 2);
    uint32_t qh[2][4], ql[2][4];
    LDSM4(qh[0][0],qh[0][1],qh[0][2],qh[0][3], smb + OFF_QHI + arow2);
    LDSM4(qh[1][0],qh[1][1],qh[1][2],qh[1][3], smb + OFF_QHI + arow2 + 32);
    LDSM4(ql[0][0],ql[0][1],ql[0][2],ql[0][3], smb + OFF_QLO + arow2);
    LDSM4(ql[1][0],ql[1][1],ql[1][2],ql[1][3], smb + OFF_QLO + arow2 + 32);

    float oacc[4][4];
    #pragma unroll
    for (int t = 0; t < 4; t++)
        #pragma unroll
        for (int i = 0; i < 4; i++) oacc[t][i] = 0.0f;
    float rsum0 = 0.0f, rsum1 = 0.0f;

    const int row0 = 16 * w + g;
    const float* mrow0 = mask + ((size_t)h * NTOK + row0) * NTOK;
    const float* mrow1 = mrow0 + 8 * NTOK;

    #pragma unroll
    for (int cchunk = 0; cchunk < 2; cchunk++) {
        const int nb0 = cchunk * 72;

        // ---- S = Q K^T for 9 n-tiles (3-MMA bf16 split, k=32) ----
        float s[9][4];
        #pragma unroll
        for (int j = 0; j < 9; j++) {
            const int n0 = nb0 + 8 * j;
            const uint32_t brow2 = (uint32_t)(((n0 + (lane & 7)) * STR + (lane >> 3) * 8) * 2);
            uint32_t bh[4], bl[4];
            LDSM4(bh[0],bh[1],bh[2],bh[3], smb + OFF_KHI + brow2);
            LDSM4(bl[0],bl[1],bl[2],bl[3], smb + OFF_KLO + brow2);
            s[j][0] = 0.f; s[j][1] = 0.f; s[j][2] = 0.f; s[j][3] = 0.f;
            MMA16816(s[j], qh[0][0],qh[0][1],qh[0][2],qh[0][3], bh[0],bh[1]);
            MMA16816(s[j], qh[1][0],qh[1][1],qh[1][2],qh[1][3], bh[2],bh[3]);
            MMA16816(s[j], qh[0][0],qh[0][1],qh[0][2],qh[0][3], bl[0],bl[1]);
            MMA16816(s[j], qh[1][0],qh[1][1],qh[1][2],qh[1][3], bl[2],bl[3]);
            MMA16816(s[j], ql[0][0],ql[0][1],ql[0][2],ql[0][3], bh[0],bh[1]);
            MMA16816(s[j], ql[1][0],ql[1][1],ql[1][2],ql[1][3], bh[2],bh[3]);
        }

        // ---- mask add + exp (poly, no MUFU) + pack to bf16 hi/lo A-frags ----
        uint32_t ph[9][2], pl[9][2];
        #pragma unroll
        for (int j = 0; j < 9; j++) {
            const int col = nb0 + 8 * j + 2 * tig;
            float2 m0 = *(const float2*)(mrow0 + col);
            float2 m1 = *(const float2*)(mrow1 + col);
            float e0 = fexp(s[j][0] + m0.x);
            float e1 = fexp(s[j][1] + m0.y);
            float e2 = fexp(s[j][2] + m1.x);
            float e3 = fexp(s[j][3] + m1.y);
            rsum0 += e0 + e1;
            rsum1 += e2 + e3;
            split2(e0, e1, ph[j][0], pl[j][0]);
            split2(e2, e3, ph[j][1], pl[j][1]);
        }

        // ---- O += P V  (P from registers; V via trans-ldmatrix) ----
        // x4 trans addressing for a k16 x n16 block:
        //   lanes 0-15 -> rows k0+(lane&15), lanes 16-31 -> same rows, +8 cols
        #pragma unroll
        for (int kt = 0; kt < 4; kt++) {
            const int k0 = nb0 + 16 * kt;
            const uint32_t vrow2 =
                (uint32_t)(((k0 + (lane & 15)) * STR + (lane >> 4) * 8) * 2);
            uint32_t bh0[4], bh1[4], bl0[4], bl1[4];
            LDSM4T(bh0[0],bh0[1],bh0[2],bh0[3], smb + OFF_VHI + vrow2);        // n 0-15
            LDSM4T(bh1[0],bh1[1],bh1[2],bh1[3], smb + OFF_VHI + vrow2 + 32);   // n 16-31
            LDSM4T(bl0[0],bl0[1],bl0[2],bl0[3], smb + OFF_VLO + vrow2);
            LDSM4T(bl1[0],bl1[1],bl1[2],bl1[3], smb + OFF_VLO + vrow2 + 32);
            const uint32_t a0h = ph[2*kt][0],   a1h = ph[2*kt][1];
            const uint32_t a2h = ph[2*kt+1][0], a3h = ph[2*kt+1][1];
            const uint32_t a0l = pl[2*kt][0],   a1l = pl[2*kt][1];
            const uint32_t a2l = pl[2*kt+1][0], a3l = pl[2*kt+1][1];
            MMA16816(oacc[0], a0h,a1h,a2h,a3h, bh0[0],bh0[1]);
            MMA16816(oacc[1], a0h,a1h,a2h,a3h, bh0[2],bh0[3]);
            MMA16816(oacc[2], a0h,a1h,a2h,a3h, bh1[0],bh1[1]);
            MMA16816(oacc[3], a0h,a1h,a2h,a3h, bh1[2],bh1[3]);
            MMA16816(oacc[0], a0h,a1h,a2h,a3h, bl0[0],bl0[1]);
            MMA16816(oacc[1], a0h,a1h,a2h,a3h, bl0[2],bl0[3]);
            MMA16816(oacc[2], a0h,a1h,a2h,a3h, bl1[0],bl1[1]);
            MMA16816(oacc[3], a0h,a1h,a2h,a3h, bl1[2],bl1[3]);
            MMA16816(oacc[0], a0l,a1l,a2l,a3l, bh0[0],bh0[1]);
            MMA16816(oacc[1], a0l,a1l,a2l,a3l, bh0[2],bh0[3]);
            MMA16816(oacc[2], a0l,a1l,a2l,a3l, bh1[0],bh1[1]);
            MMA16816(oacc[3], a0l,a1l,a2l,a3l, bh1[2],bh1[3]);
        }
        {   // tail: k8 (chunk cols nb0+64..nb0+71, S tile j=8)
            const int k0 = nb0 + 64;
            const uint32_t vr2 = (uint32_t)(((k0 + (lane & 7)) * STR) * 2);
            const uint32_t off8 = (uint32_t)(((lane >> 3) & 1) * 16);  // +8 cols for mat 1
            uint32_t th0[2], th1[2], tl0[2], tl1[2];
            LDSM2T(th0[0],th0[1], smb + OFF_VHI + vr2 + off8);         // n 0-7, 8-15
            LDSM2T(th1[0],th1[1], smb + OFF_VHI + vr2 + 32 + off8);    // n 16-23, 24-31
            LDSM2T(tl0[0],tl0[1], smb + OFF_VLO + vr2 + off8);
            LDSM2T(tl1[0],tl1[1], smb + OFF_VLO + vr2 + 32 + off8);
            const uint32_t a0h = ph[8][0], a1h = ph[8][1];
            const uint32_t a0l = pl[8][0], a1l = pl[8][1];
            MMA16808(oacc[0], a0h,a1h, th0[0]);
            MMA16808(oacc[1], a0h,a1h, th0[1]);
            MMA16808(oacc[2], a0h,a1h, th1[0]);
            MMA16808(oacc[3], a0h,a1h, th1[1]);
            MMA16808(oacc[0], a0h,a1h, tl0[0]);
            MMA16808(oacc[1], a0h,a1h, tl0[1]);
            MMA16808(oacc[2], a0h,a1h, tl1[0]);
            MMA16808(oacc[3], a0h,a1h, tl1[1]);
            MMA16808(oacc[0], a0l,a1l, th0[0]);
            MMA16808(oacc[1], a0l,a1l, th0[1]);
            MMA16808(oacc[2], a0l,a1l, th1[0]);
            MMA16808(oacc[3], a0l,a1l, th1[1]);
        }
    }

    // ---- normalize (sum reduce over quad) + write ----
    rsum0 += __shfl_xor_sync(0xFFFFFFFFu, rsum0, 1);
    rsum0 += __shfl_xor_sync(0xFFFFFFFFu, rsum0, 2);
    rsum1 += __shfl_xor_sync(0xFFFFFFFFu, rsum1, 1);
    rsum1 += __shfl_xor_sync(0xFFFFFFFFu, rsum1, 2);
    const float inv0 = 1.0f / rsum0, inv1 = 1.0f / rsum1;

    float* op0 = out + ((size_t)b * NTOK + row0) * 128 + h * DH;
    float* op1 = op0 + 8 * 128;
    #pragma unroll
    for (int t = 0; t < 4; t++) {
        const int col = 8 * t + 2 * tig;
        *(float2*)(op0 + col) = make_float2(oacc[t][0] * inv0, oacc[t][1] * inv0);
        *(float2*)(op1 + col) = make_float2(oacc[t][2] * inv1, oacc[t][3] * inv1);
    }
}

extern "C" void kernel_launch(void* const* d_in, const int* in_sizes, int n_in,
                              void* d_out, int out_size) {
    const float* qkv  = (const float*)d_in[0];
    const float* mask = (const float*)d_in[1];
    float* out = (float*)d_out;

    cudaFuncSetAttribute(attn_kernel,
                         cudaFuncAttributeMaxDynamicSharedMemorySize, SMEM_BYTES);

    dim3 grid(HEADS, 2048);
    attn_kernel<<<grid, 288, SMEM_BYTES>>>(qkv, mask, out);
}

// round 8
// speedup vs baseline: 5.2495x; 1.6148x over previous
#include <cuda_runtime.h>
#include <cuda_fp16.h>
#include <cstdint>

#define NTOK 144
#define HEADS 4
#define CC 384
#define DH 32
#define STR 40             // fp16 elems per smem row (80B) -> ldmatrix conflict-free
#define SCALE 0.17677669529663687f

#define TSZ (NTOK*STR*2)   // 11520 B per tensor plane
#define OFF_Q 0
#define OFF_K (1*TSZ)
#define OFF_V (2*TSZ)
#define SMEM_BYTES (3*TSZ) // 34560 B

#define LDSM4(r0,r1,r2,r3,addr) \
    asm volatile("ldmatrix.sync.aligned.m8n8.x4.shared.b16 {%0,%1,%2,%3}, [%4];" \
        : "=r"(r0),"=r"(r1),"=r"(r2),"=r"(r3) : "r"(addr))
#define LDSM4T(r0,r1,r2,r3,addr) \
    asm volatile("ldmatrix.sync.aligned.m8n8.x4.trans.shared.b16 {%0,%1,%2,%3}, [%4];" \
        : "=r"(r0),"=r"(r1),"=r"(r2),"=r"(r3) : "r"(addr))
#define LDSM2T(r0,r1,addr) \
    asm volatile("ldmatrix.sync.aligned.m8n8.x2.trans.shared.b16 {%0,%1}, [%2];" \
        : "=r"(r0),"=r"(r1) : "r"(addr))
#define MMAF16(c,a0,a1,a2,a3,b0,b1) \
    asm volatile("mma.sync.aligned.m16n8k16.row.col.f32.f16.f16.f32 " \
        "{%0,%1,%2,%3}, {%4,%5,%6,%7}, {%8,%9}, {%0,%1,%2,%3};" \
        : "+f"(c[0]),"+f"(c[1]),"+f"(c[2]),"+f"(c[3]) \
        : "r"(a0),"r"(a1),"r"(a2),"r"(a3),"r"(b0),"r"(b1))
#define MMAF16K8(c,a0,a1,b0) \
    asm volatile("mma.sync.aligned.m16n8k8.row.col.f32.f16.f16.f32 " \
        "{%0,%1,%2,%3}, {%4,%5}, {%6}, {%0,%1,%2,%3};" \
        : "+f"(c[0]),"+f"(c[1]),"+f"(c[2]),"+f"(c[3]) \
        : "r"(a0),"r"(a1),"r"(b0))

// exp on fma/alu pipes (no MUFU): 2^(x*log2e), deg-5 poly + exponent-bit scale
__device__ __forceinline__ float fexp(float x) {
    x = fmaxf(x, -80.0f);
    float t = x * 1.4426950408889634f;
    float r = rintf(t);
    float f = t - r;
    float p = 1.33336498e-3f;
    p = fmaf(p, f, 9.61793571e-3f);
    p = fmaf(p, f, 5.55043442e-2f);
    p = fmaf(p, f, 2.40226507e-1f);
    p = fmaf(p, f, 6.93147182e-1f);
    p = fmaf(p, f, 1.0f);
    return __int_as_float(__float_as_int(p) + (((int)r) << 23));
}

__device__ __forceinline__ void cvt_store(float4 v, __half* p) {
    union { __half2 h[2]; uint2 u; } U;
    U.h[0] = __floats2half2_rn(v.x, v.y);
    U.h[1] = __floats2half2_rn(v.z, v.w);
    *(uint2*)p = U.u;
}

__device__ __forceinline__ uint32_t pack2(float a, float b) {
    union { __half2 h; uint32_t u; } U;
    U.h = __floats2half2_rn(a, b);
    return U.u;
}

__global__ __launch_bounds__(288, 3)
void attn_kernel(const float* __restrict__ qkv,
                 const float* __restrict__ mask,
                 float* __restrict__ out)
{
    extern __shared__ char smc[];
    const uint32_t smb = (uint32_t)__cvta_generic_to_shared(smc);
    const int h = blockIdx.x, b = blockIdx.y;
    const int tid = threadIdx.x, w = tid >> 5, lane = tid & 31;
    const int g = lane >> 2, tig = lane & 3;

    __half* Qs = (__half*)(smc + OFF_Q);
    __half* Ks = (__half*)(smc + OFF_K);
    __half* Vs = (__half*)(smc + OFF_V);

    // ---- load Q (pre-scaled), K, V -> fp16 smem ----
    const float* base = qkv + (size_t)b * NTOK * CC;
    for (int i = tid; i < NTOK * 8; i += 288) {
        int r = i >> 3, f = (i & 7) * 4;
        float4 qv = *(const float4*)(base + r * CC + h * DH + f);
        qv.x *= SCALE; qv.y *= SCALE; qv.z *= SCALE; qv.w *= SCALE;
        cvt_store(qv, Qs + r * STR + f);
        cvt_store(*(const float4*)(base + r * CC + 128 + h * DH + f), Ks + r * STR + f);
        cvt_store(*(const float4*)(base + r * CC + 256 + h * DH + f), Vs + r * STR + f);
    }
    __syncthreads();

    // ---- Q A-fragments (k=32 -> two k16 frags) ----
    const uint32_t arow2 = (uint32_t)(((16 * w + (lane & 15)) * STR + (lane >> 4) * 8) * 2);
    uint32_t qf[2][4];
    LDSM4(qf[0][0],qf[0][1],qf[0][2],qf[0][3], smb + OFF_Q + arow2);
    LDSM4(qf[1][0],qf[1][1],qf[1][2],qf[1][3], smb + OFF_Q + arow2 + 32);

    float oacc[4][4];
    #pragma unroll
    for (int t = 0; t < 4; t++)
        #pragma unroll
        for (int i = 0; i < 4; i++) oacc[t][i] = 0.0f;
    float rsum0 = 0.0f, rsum1 = 0.0f;

    const int row0 = 16 * w + g;
    const float* mrow0 = mask + ((size_t)h * NTOK + row0) * NTOK;
    const float* mrow1 = mrow0 + 8 * NTOK;

    #pragma unroll
    for (int cchunk = 0; cchunk < 2; cchunk++) {
        const int nb0 = cchunk * 72;

        // ---- S = Q K^T for 9 n-tiles (k=32) ----
        float s[9][4];
        #pragma unroll
        for (int j = 0; j < 9; j++) {
            const int n0 = nb0 + 8 * j;
            const uint32_t brow2 = (uint32_t)(((n0 + (lane & 7)) * STR + (lane >> 3) * 8) * 2);
            uint32_t bf[4];
            LDSM4(bf[0],bf[1],bf[2],bf[3], smb + OFF_K + brow2);
            s[j][0] = 0.f; s[j][1] = 0.f; s[j][2] = 0.f; s[j][3] = 0.f;
            MMAF16(s[j], qf[0][0],qf[0][1],qf[0][2],qf[0][3], bf[0],bf[1]);
            MMAF16(s[j], qf[1][0],qf[1][1],qf[1][2],qf[1][3], bf[2],bf[3]);
        }

        // ---- mask add + exp (poly) + pack to fp16 A-frags ----
        uint32_t pf[9][2];
        #pragma unroll
        for (int j = 0; j < 9; j++) {
            const int col = nb0 + 8 * j + 2 * tig;
            float2 m0 = *(const float2*)(mrow0 + col);
            float2 m1 = *(const float2*)(mrow1 + col);
            float e0 = fexp(s[j][0] + m0.x);
            float e1 = fexp(s[j][1] + m0.y);
            float e2 = fexp(s[j][2] + m1.x);
            float e3 = fexp(s[j][3] + m1.y);
            rsum0 += e0 + e1;
            rsum1 += e2 + e3;
            pf[j][0] = pack2(e0, e1);
            pf[j][1] = pack2(e2, e3);
        }

        // ---- O += P V  (P from registers; V via trans-ldmatrix) ----
        #pragma unroll
        for (int kt = 0; kt < 4; kt++) {
            const int k0 = nb0 + 16 * kt;
            const uint32_t vrow2 =
                (uint32_t)(((k0 + (lane & 15)) * STR + (lane >> 4) * 8) * 2);
            uint32_t v0[4], v1[4];
            LDSM4T(v0[0],v0[1],v0[2],v0[3], smb + OFF_V + vrow2);        // n 0-15
            LDSM4T(v1[0],v1[1],v1[2],v1[3], smb + OFF_V + vrow2 + 32);   // n 16-31
            const uint32_t a0 = pf[2*kt][0],   a1 = pf[2*kt][1];
            const uint32_t a2 = pf[2*kt+1][0], a3 = pf[2*kt+1][1];
            MMAF16(oacc[0], a0,a1,a2,a3, v0[0],v0[1]);
            MMAF16(oacc[1], a0,a1,a2,a3, v0[2],v0[3]);
            MMAF16(oacc[2], a0,a1,a2,a3, v1[0],v1[1]);
            MMAF16(oacc[3], a0,a1,a2,a3, v1[2],v1[3]);
        }
        {   // tail: k8 (chunk cols nb0+64..nb0+71, S tile j=8)
            const int k0 = nb0 + 64;
            const uint32_t vr2 = (uint32_t)(((k0 + (lane & 7)) * STR) * 2);
            const uint32_t off8 = (uint32_t)(((lane >> 3) & 1) * 16);  // +8 cols for mat 1
            uint32_t t0[2], t1[2];
            LDSM2T(t0[0],t0[1], smb + OFF_V + vr2 + off8);         // n 0-7, 8-15
            LDSM2T(t1[0],t1[1], smb + OFF_V + vr2 + 32 + off8);    // n 16-23, 24-31
            const uint32_t a0 = pf[8][0], a1 = pf[8][1];
            MMAF16K8(oacc[0], a0,a1, t0[0]);
            MMAF16K8(oacc[1], a0,a1, t0[1]);
            MMAF16K8(oacc[2], a0,a1, t1[0]);
            MMAF16K8(oacc[3], a0,a1, t1[1]);
        }
    }

    // ---- normalize (sum reduce over quad) + write ----
    rsum0 += __shfl_xor_sync(0xFFFFFFFFu, rsum0, 1);
    rsum0 += __shfl_xor_sync(0xFFFFFFFFu, rsum0, 2);
    rsum1 += __shfl_xor_sync(0xFFFFFFFFu, rsum1, 1);
    rsum1 += __shfl_xor_sync(0xFFFFFFFFu, rsum1, 2);
    const float inv0 = 1.0f / rsum0, inv1 = 1.0f / rsum1;

    float* op0 = out + ((size_t)b * NTOK + row0) * 128 + h * DH;
    float* op1 = op0 + 8 * 128;
    #pragma unroll
    for (int t = 0; t < 4; t++) {
        const int col = 8 * t + 2 * tig;
        *(float2*)(op0 + col) = make_float2(oacc[t][0] * inv0, oacc[t][1] * inv0);
        *(float2*)(op1 + col) = make_float2(oacc[t][2] * inv1, oacc[t][3] * inv1);
    }
}

extern "C" void kernel_launch(void* const* d_in, const int* in_sizes, int n_in,
                              void* d_out, int out_size) {
    const float* qkv  = (const float*)d_in[0];
    const float* mask = (const float*)d_in[1];
    float* out = (float*)d_out;

    cudaFuncSetAttribute(attn_kernel,
                         cudaFuncAttributeMaxDynamicSharedMemorySize, SMEM_BYTES);

    dim3 grid(HEADS, 2048);
    attn_kernel<<<grid, 288, SMEM_BYTES>>>(qkv, mask, out);
}